// round 4
// baseline (speedup 1.0000x reference)
#include <cuda_runtime.h>
#include <cuda_bf16.h>
#include <cstdint>

// Output pattern, shape [2, G*N*N] flattened row-major, FLOAT32 values:
//   half 0: out[g*N*N + i]     = float(i / N)   (row index)
//   half 1: out[H + g*N*N + i] = float(i % N)   (col index),  H = G*N*N
// Pure write-only stream (512 MiB for N=4096, G=4). Inputs' values unused.
// N from shape algebra: out_size = 2*G*N*N with small integer G.

// Fast path: N % 16 == 0. Each thread writes 16 consecutive elements (4x
// float4, 64B) in each half, via streaming (evict-first) stores — the output
// is 4x L2 capacity and never re-read, so don't let it churn L2.
__global__ void fa_vec16_kernel(float* __restrict__ out,
                                unsigned N, unsigned NN, long long halfElems) {
    unsigned i16 = ((unsigned)blockIdx.x * blockDim.x + threadIdx.x) * 16u;
    if (i16 >= NN) return;
    unsigned r = i16 / N;          // constant across the 16-group (N%16==0)
    unsigned c = i16 - r * N;
    long long base = (long long)blockIdx.y * (long long)NN + (long long)i16;

    float rf = (float)r;
    float cf = (float)c;
    float4 rv = make_float4(rf, rf, rf, rf);

    float4* p0 = reinterpret_cast<float4*>(out + base);
    float4* p1 = reinterpret_cast<float4*>(out + halfElems + base);
#pragma unroll
    for (int j = 0; j < 4; j++) {
        __stcs(p0 + j, rv);
        float b = cf + (float)(4 * j);
        __stcs(p1 + j, make_float4(b, b + 1.0f, b + 2.0f, b + 3.0f));
    }
}

// Mid path: N % 4 == 0.
__global__ void fa_vec4_kernel(float* __restrict__ out,
                               unsigned N, unsigned NN, long long halfElems) {
    unsigned i4 = ((unsigned)blockIdx.x * blockDim.x + threadIdx.x) * 4u;
    if (i4 >= NN) return;
    unsigned r = i4 / N;
    unsigned c = i4 - r * N;
    long long base = (long long)blockIdx.y * (long long)NN + (long long)i4;
    float rf = (float)r, cf = (float)c;
    __stcs(reinterpret_cast<float4*>(out + base),
           make_float4(rf, rf, rf, rf));
    __stcs(reinterpret_cast<float4*>(out + halfElems + base),
           make_float4(cf, cf + 1.0f, cf + 2.0f, cf + 3.0f));
}

// Scalar fallback.
__global__ void fa_scalar_kernel(float* __restrict__ out,
                                 unsigned N, unsigned NN, long long halfElems) {
    unsigned i = (unsigned)blockIdx.x * blockDim.x + threadIdx.x;
    if (i >= NN) return;
    unsigned r = i / N;
    unsigned c = i - r * N;
    long long base = (long long)blockIdx.y * (long long)NN + (long long)i;
    out[base] = (float)r;
    out[halfElems + base] = (float)c;
}

extern "C" void kernel_launch(void* const* d_in, const int* in_sizes, int n_in,
                              void* d_out, int out_size) {
    (void)d_in;
    // Derive N: the input size s with out_size == 2*G*s*s, integer 1<=G<=4096.
    long long N = 0, G = 0;
    for (int i = 0; i < n_in; i++) {
        long long s = (long long)in_sizes[i];
        if (s <= 0) continue;
        long long denom = 2LL * s * s;
        if (denom <= 0) continue;
        if ((long long)out_size % denom != 0) continue;
        long long g = (long long)out_size / denom;
        if (g >= 1 && g <= 4096) { N = s; G = g; break; }
    }
    if (N == 0) {
        N = (long long)in_sizes[2];
        long long denom = 2LL * N * N;
        G = (denom > 0 && (long long)out_size % denom == 0)
                ? (long long)out_size / denom : 1;
    }

    const long long NNll = N * N;
    const unsigned NN = (unsigned)NNll;
    const long long halfElems = G * NNll;
    float* out = (float*)d_out;
    const int threads = 256;

    if ((N % 16) == 0 && NNll <= 0xFFFFFFFFLL) {
        const unsigned elems16 = NN / 16u;
        unsigned gx = (elems16 + threads - 1) / threads;
        if (gx == 0) gx = 1;
        dim3 grid(gx, (unsigned)G, 1);
        fa_vec16_kernel<<<grid, threads>>>(out, (unsigned)N, NN, halfElems);
    } else if ((N % 4) == 0 && NNll <= 0xFFFFFFFFLL) {
        const unsigned elems4 = NN / 4u;
        unsigned gx = (elems4 + threads - 1) / threads;
        if (gx == 0) gx = 1;
        dim3 grid(gx, (unsigned)G, 1);
        fa_vec4_kernel<<<grid, threads>>>(out, (unsigned)N, NN, halfElems);
    } else {
        unsigned gx = (unsigned)((NNll + threads - 1) / threads);
        if (gx == 0) gx = 1;
        dim3 grid(gx, (unsigned)G, 1);
        fa_scalar_kernel<<<grid, threads>>>(out, (unsigned)N, NN, halfElems);
    }
}

// round 5
// speedup vs baseline: 1.8501x; 1.8501x over previous
#include <cuda_runtime.h>
#include <cuda_bf16.h>
#include <cstdint>

// Output pattern, shape [2, G*N*N] flattened row-major, FLOAT32 values:
//   half 0: out[g*N*N + i]     = float(i / N)   (row index)
//   half 1: out[H + g*N*N + i] = float(i % N)   (col index),  H = G*N*N
// Pure write-only stream (512 MiB for N=4096, G=4). Inputs' values unused.
//
// Layout rule learned in R4: each thread owns EXACTLY one contiguous float4
// per half so every warp covers a contiguous, fully-written 2KB span —
// anything wider per-thread fractures 128B lines and triggers L2/HBM
// read-modify-write (2x traffic). Streaming stores (__stcs) because the
// output is 4x L2 capacity and never re-read.

__global__ void fa_vec_kernel(float* __restrict__ out,
                              unsigned N, unsigned NN, long long halfElems) {
    unsigned i4 = ((unsigned)blockIdx.x * blockDim.x + threadIdx.x) * 4u;
    if (i4 >= NN) return;
    unsigned r = i4 / N;           // row index (constant across the 4-group)
    unsigned c = i4 - r * N;       // col index of first element
    long long base = (long long)blockIdx.y * (long long)NN + (long long)i4;

    float rf = (float)r;
    float cf = (float)c;

    __stcs(reinterpret_cast<float4*>(out + base),
           make_float4(rf, rf, rf, rf));
    __stcs(reinterpret_cast<float4*>(out + halfElems + base),
           make_float4(cf, cf + 1.0f, cf + 2.0f, cf + 3.0f));
}

// Scalar fallback (N % 4 != 0 — not expected for this problem's shapes).
__global__ void fa_scalar_kernel(float* __restrict__ out,
                                 unsigned N, unsigned NN, long long halfElems) {
    unsigned i = (unsigned)blockIdx.x * blockDim.x + threadIdx.x;
    if (i >= NN) return;
    unsigned r = i / N;
    unsigned c = i - r * N;
    long long base = (long long)blockIdx.y * (long long)NN + (long long)i;
    out[base] = (float)r;
    out[halfElems + base] = (float)c;
}

extern "C" void kernel_launch(void* const* d_in, const int* in_sizes, int n_in,
                              void* d_out, int out_size) {
    (void)d_in;
    // Derive N: the input size s with out_size == 2*G*s*s, integer 1<=G<=4096.
    long long N = 0, G = 0;
    for (int i = 0; i < n_in; i++) {
        long long s = (long long)in_sizes[i];
        if (s <= 0) continue;
        long long denom = 2LL * s * s;
        if (denom <= 0) continue;
        if ((long long)out_size % denom != 0) continue;
        long long g = (long long)out_size / denom;
        if (g >= 1 && g <= 4096) { N = s; G = g; break; }
    }
    if (N == 0) {
        N = (long long)in_sizes[2];
        long long denom = 2LL * N * N;
        G = (denom > 0 && (long long)out_size % denom == 0)
                ? (long long)out_size / denom : 1;
    }

    const long long NNll = N * N;
    const unsigned NN = (unsigned)NNll;
    const long long halfElems = G * NNll;
    float* out = (float*)d_out;
    const int threads = 256;

    if ((N % 4) == 0 && NNll <= 0xFFFFFFFFLL) {
        const unsigned elems4 = NN / 4u;
        unsigned gx = (elems4 + threads - 1) / threads;
        if (gx == 0) gx = 1;
        dim3 grid(gx, (unsigned)G, 1);
        fa_vec_kernel<<<grid, threads>>>(out, (unsigned)N, NN, halfElems);
    } else {
        unsigned gx = (unsigned)((NNll + threads - 1) / threads);
        if (gx == 0) gx = 1;
        dim3 grid(gx, (unsigned)G, 1);
        fa_scalar_kernel<<<grid, threads>>>(out, (unsigned)N, NN, halfElems);
    }
}

// round 6
// speedup vs baseline: 1.8565x; 1.0034x over previous
#include <cuda_runtime.h>
#include <cuda_bf16.h>
#include <cstdint>

// Output pattern, shape [2, G*N*N] flattened row-major, FLOAT32 values:
//   half 0: out[g*N*N + i]     = float(i / N)   (row index)
//   half 1: out[H + g*N*N + i] = float(i % N)   (col index),  H = G*N*N
// Pure write-only stream (512 MiB for N=4096, G=4); inputs' values unused.
//
// R4 lesson: per-STG warp footprint must be a contiguous, fully-covered 2KB
// span (thread = one float4). R5 lesson: we sit at the HBM write ceiling
// (~7.4 TB/s achieved). This version improves DRAM burst locality: one block
// owns one full 16KB row per half (blockIdx.y = row, blockIdx.z = graph),
// iterating along the WARP axis, and removes the integer div entirely.

// Fast path: N % (256*4) == 0 (N=4096 ok). Block = one row of one graph.
__global__ void fa_row_kernel(float* __restrict__ out,
                              unsigned N, long long halfElems) {
    const unsigned r = blockIdx.y;                 // row index
    const long long NNll = (long long)N * (long long)N;
    long long base = (long long)blockIdx.z * NNll
                   + (long long)r * (long long)N
                   + (long long)(threadIdx.x * 4u);

    const float rf = (float)r;
    const float4 rv = make_float4(rf, rf, rf, rf);
    const unsigned iters = N / (blockDim.x * 4u);  // 4 for N=4096, 256 thr
    const unsigned stride = blockDim.x * 4u;       // 1024 floats

    float c = (float)(threadIdx.x * 4u);
    for (unsigned j = 0; j < iters; j++) {
        __stcs(reinterpret_cast<float4*>(out + base), rv);
        __stcs(reinterpret_cast<float4*>(out + halfElems + base),
               make_float4(c, c + 1.0f, c + 2.0f, c + 3.0f));
        base += stride;
        c += (float)stride;
    }
}

// Generic path (R5 kernel): thread = one float4 per half, N % 4 == 0.
__global__ void fa_vec_kernel(float* __restrict__ out,
                              unsigned N, unsigned NN, long long halfElems) {
    unsigned i4 = ((unsigned)blockIdx.x * blockDim.x + threadIdx.x) * 4u;
    if (i4 >= NN) return;
    unsigned r = i4 / N;
    unsigned c = i4 - r * N;
    long long base = (long long)blockIdx.y * (long long)NN + (long long)i4;
    float rf = (float)r, cf = (float)c;
    __stcs(reinterpret_cast<float4*>(out + base),
           make_float4(rf, rf, rf, rf));
    __stcs(reinterpret_cast<float4*>(out + halfElems + base),
           make_float4(cf, cf + 1.0f, cf + 2.0f, cf + 3.0f));
}

// Scalar fallback.
__global__ void fa_scalar_kernel(float* __restrict__ out,
                                 unsigned N, unsigned NN, long long halfElems) {
    unsigned i = (unsigned)blockIdx.x * blockDim.x + threadIdx.x;
    if (i >= NN) return;
    unsigned r = i / N;
    unsigned c = i - r * N;
    long long base = (long long)blockIdx.y * (long long)NN + (long long)i;
    out[base] = (float)r;
    out[halfElems + base] = (float)c;
}

extern "C" void kernel_launch(void* const* d_in, const int* in_sizes, int n_in,
                              void* d_out, int out_size) {
    (void)d_in;
    // Derive N: the input size s with out_size == 2*G*s*s, integer 1<=G<=4096.
    long long N = 0, G = 0;
    for (int i = 0; i < n_in; i++) {
        long long s = (long long)in_sizes[i];
        if (s <= 0) continue;
        long long denom = 2LL * s * s;
        if (denom <= 0) continue;
        if ((long long)out_size % denom != 0) continue;
        long long g = (long long)out_size / denom;
        if (g >= 1 && g <= 4096) { N = s; G = g; break; }
    }
    if (N == 0) {
        N = (long long)in_sizes[2];
        long long denom = 2LL * N * N;
        G = (denom > 0 && (long long)out_size % denom == 0)
                ? (long long)out_size / denom : 1;
    }

    const long long NNll = N * N;
    const unsigned NN = (unsigned)NNll;
    const long long halfElems = G * NNll;
    float* out = (float*)d_out;
    const int threads = 256;

    if ((N % (threads * 4)) == 0 && N <= 65535LL * 1 && G <= 65535LL) {
        // Row kernel: grid (1, N, G), each block writes one 16KB row per half.
        dim3 grid(1, (unsigned)N, (unsigned)G);
        fa_row_kernel<<<grid, threads>>>(out, (unsigned)N, halfElems);
    } else if ((N % 4) == 0 && NNll <= 0xFFFFFFFFLL) {
        const unsigned elems4 = NN / 4u;
        unsigned gx = (elems4 + threads - 1) / threads;
        if (gx == 0) gx = 1;
        dim3 grid(gx, (unsigned)G, 1);
        fa_vec_kernel<<<grid, threads>>>(out, (unsigned)N, NN, halfElems);
    } else {
        unsigned gx = (unsigned)((NNll + threads - 1) / threads);
        if (gx == 0) gx = 1;
        dim3 grid(gx, (unsigned)G, 1);
        fa_scalar_kernel<<<grid, threads>>>(out, (unsigned)N, NN, halfElems);
    }
}

// round 7
// speedup vs baseline: 1.8573x; 1.0004x over previous
#include <cuda_runtime.h>
#include <cuda_bf16.h>
#include <cstdint>

// Output pattern, shape [2, G*N*N] flattened row-major, FLOAT32 values:
//   half 0: out[g*N*N + i]     = float(i / N)   (row index)
//   half 1: out[H + g*N*N + i] = float(i % N)   (col index),  H = G*N*N
// Pure write-only stream (512 MiB for N=4096, G=4); inputs' values unused.
//
// Lessons: (R4) per-STG warp footprint must be a contiguous fully-covered 2KB
// span; (R5/R6) we sit at the HBM write ceiling (~7.45 TB/s achieved). This
// version purifies the streams: each block writes ONE 16KB row of ONE half
// (blockIdx.z selects half+graph), so no block alternates between far-apart
// address ranges. __stcs keeps the 512MB never-re-read output from churning L2.

// Fast path: N % (256*4) == 0. grid = (1, N, 2G); z<G: row-half, z>=G: col-half.
__global__ void fa_row_split_kernel(float* __restrict__ out,
                                    unsigned N, unsigned G,
                                    long long halfElems) {
    const unsigned r = blockIdx.y;                 // row index
    const unsigned z = blockIdx.z;
    const bool colHalf = (z >= G);
    const unsigned g = colHalf ? (z - G) : z;
    const long long NNll = (long long)N * (long long)N;

    long long base = (colHalf ? halfElems : 0LL)
                   + (long long)g * NNll
                   + (long long)r * (long long)N
                   + (long long)(threadIdx.x * 4u);

    const unsigned stride = blockDim.x * 4u;       // 1024 floats
    const unsigned iters = N / stride;             // 4 for N=4096, 256 thr

    if (colHalf) {
        float c = (float)(threadIdx.x * 4u);
        for (unsigned j = 0; j < iters; j++) {
            __stcs(reinterpret_cast<float4*>(out + base),
                   make_float4(c, c + 1.0f, c + 2.0f, c + 3.0f));
            base += stride;
            c += (float)stride;
        }
    } else {
        const float rf = (float)r;
        const float4 rv = make_float4(rf, rf, rf, rf);
        for (unsigned j = 0; j < iters; j++) {
            __stcs(reinterpret_cast<float4*>(out + base), rv);
            base += stride;
        }
    }
}

// Generic path: thread = one float4 per half, N % 4 == 0.
__global__ void fa_vec_kernel(float* __restrict__ out,
                              unsigned N, unsigned NN, long long halfElems) {
    unsigned i4 = ((unsigned)blockIdx.x * blockDim.x + threadIdx.x) * 4u;
    if (i4 >= NN) return;
    unsigned r = i4 / N;
    unsigned c = i4 - r * N;
    long long base = (long long)blockIdx.y * (long long)NN + (long long)i4;
    float rf = (float)r, cf = (float)c;
    __stcs(reinterpret_cast<float4*>(out + base),
           make_float4(rf, rf, rf, rf));
    __stcs(reinterpret_cast<float4*>(out + halfElems + base),
           make_float4(cf, cf + 1.0f, cf + 2.0f, cf + 3.0f));
}

// Scalar fallback.
__global__ void fa_scalar_kernel(float* __restrict__ out,
                                 unsigned N, unsigned NN, long long halfElems) {
    unsigned i = (unsigned)blockIdx.x * blockDim.x + threadIdx.x;
    if (i >= NN) return;
    unsigned r = i / N;
    unsigned c = i - r * N;
    long long base = (long long)blockIdx.y * (long long)NN + (long long)i;
    out[base] = (float)r;
    out[halfElems + base] = (float)c;
}

extern "C" void kernel_launch(void* const* d_in, const int* in_sizes, int n_in,
                              void* d_out, int out_size) {
    (void)d_in;
    // Derive N: the input size s with out_size == 2*G*s*s, integer 1<=G<=4096.
    long long N = 0, G = 0;
    for (int i = 0; i < n_in; i++) {
        long long s = (long long)in_sizes[i];
        if (s <= 0) continue;
        long long denom = 2LL * s * s;
        if (denom <= 0) continue;
        if ((long long)out_size % denom != 0) continue;
        long long g = (long long)out_size / denom;
        if (g >= 1 && g <= 4096) { N = s; G = g; break; }
    }
    if (N == 0) {
        N = (long long)in_sizes[2];
        long long denom = 2LL * N * N;
        G = (denom > 0 && (long long)out_size % denom == 0)
                ? (long long)out_size / denom : 1;
    }

    const long long NNll = N * N;
    const unsigned NN = (unsigned)NNll;
    const long long halfElems = G * NNll;
    float* out = (float*)d_out;
    const int threads = 256;

    if ((N % (threads * 4)) == 0 && N <= 65535LL && 2 * G <= 65535LL) {
        dim3 grid(1, (unsigned)N, (unsigned)(2 * G));
        fa_row_split_kernel<<<grid, threads>>>(out, (unsigned)N, (unsigned)G,
                                               halfElems);
    } else if ((N % 4) == 0 && NNll <= 0xFFFFFFFFLL) {
        const unsigned elems4 = NN / 4u;
        unsigned gx = (elems4 + threads - 1) / threads;
        if (gx == 0) gx = 1;
        dim3 grid(gx, (unsigned)G, 1);
        fa_vec_kernel<<<grid, threads>>>(out, (unsigned)N, NN, halfElems);
    } else {
        unsigned gx = (unsigned)((NNll + threads - 1) / threads);
        if (gx == 0) gx = 1;
        dim3 grid(gx, (unsigned)G, 1);
        fa_scalar_kernel<<<grid, threads>>>(out, (unsigned)N, NN, halfElems);
    }
}